// round 1
// baseline (speedup 1.0000x reference)
#include <cuda_runtime.h>
#include <cstdint>

// Problem constants (from reference): N=50000, E=600000, IN_DIM=128, HID=256, OUT=128
#define MAXN 50000
#define DIM 128

// Scratch (device globals — no allocation allowed)
__device__ float g_msg[MAXN * DIM];   // 25.6 MB: neighbor sums, then scaled means
__device__ int   g_deg[MAXN];
__device__ float g_W[256 * 128];      // fused W1@W2
__device__ float g_b[128];            // fused b1@W2 + b2

// ---------------------------------------------------------------------------
// Kernel 1: fuse the two linear layers (no inner activation => collapse)
// blocks 0..255 compute row i of W = W1@W2 ; block 256 computes bias
// ---------------------------------------------------------------------------
__global__ void fuse_weights(const float* __restrict__ W1, const float* __restrict__ b1,
                             const float* __restrict__ W2, const float* __restrict__ b2) {
    int row = blockIdx.x;
    int j = threadIdx.x;            // 0..127
    if (row < 256) {
        float acc = 0.f;
        #pragma unroll 4
        for (int k = 0; k < 256; k++)
            acc += W1[row * 256 + k] * W2[k * 128 + j];
        g_W[row * 128 + j] = acc;
    } else {
        float acc = b2[j];
        #pragma unroll 4
        for (int k = 0; k < 256; k++)
            acc += b1[k] * W2[k * 128 + j];
        g_b[j] = acc;
    }
}

// ---------------------------------------------------------------------------
// Kernel 2: zero accumulators
// ---------------------------------------------------------------------------
__global__ void zero_buffers(int n) {
    int idx = blockIdx.x * blockDim.x + threadIdx.x;
    int total4 = n * (DIM / 4);
    if (idx < total4)
        reinterpret_cast<float4*>(g_msg)[idx] = make_float4(0.f, 0.f, 0.f, 0.f);
    if (idx < n)
        g_deg[idx] = 0;
}

// ---------------------------------------------------------------------------
// Kernel 3: edge scatter. One warp per edge; lane l handles floats [4l,4l+4).
// Vector reduction (red.global.add.v4.f32, sm_90+) — no return trip.
// ---------------------------------------------------------------------------
__global__ void scatter_edges(const float* __restrict__ h,
                              const int* __restrict__ src,
                              const int* __restrict__ dst, int E) {
    int warp = (blockIdx.x * blockDim.x + threadIdx.x) >> 5;
    int lane = threadIdx.x & 31;
    if (warp >= E) return;
    int s = src[warp];   // all lanes same addr -> single broadcast request
    int d = dst[warp];
    float4 v = reinterpret_cast<const float4*>(h)[(size_t)s * (DIM / 4) + lane];
    float* p = &g_msg[(size_t)d * DIM + lane * 4];
    asm volatile("red.global.add.v4.f32 [%0], {%1,%2,%3,%4};"
                 :: "l"(p), "f"(v.x), "f"(v.y), "f"(v.z), "f"(v.w) : "memory");
    if (lane == 0) atomicAdd(&g_deg[d], 1);
}

// ---------------------------------------------------------------------------
// Kernel 4: scale msg by 1/max(deg,1) in place  (mean aggregation)
// ---------------------------------------------------------------------------
__global__ void scale_msg(int n) {
    int idx = blockIdx.x * blockDim.x + threadIdx.x;   // per float4
    int total4 = n * (DIM / 4);
    if (idx >= total4) return;
    int node = idx >> 5;  // 32 float4 per node
    float inv = 1.0f / fmaxf((float)g_deg[node], 1.0f);
    float4 v = reinterpret_cast<float4*>(g_msg)[idx];
    v.x *= inv; v.y *= inv; v.z *= inv; v.w *= inv;
    reinterpret_cast<float4*>(g_msg)[idx] = v;
}

// ---------------------------------------------------------------------------
// Kernel 5: fused GEMM + bias + relu.
//   out[n, :] = relu( [h[n,:], msg[n,:]] @ W + b )     (M=N, K=256, N=128)
// 128x128 block tile, BK=16, 8x8 per-thread, packed fma.rn.f32x2.
// ---------------------------------------------------------------------------
#define BM 128
#define BN 128
#define BK 16
#define TM 8
#define TN 8

__global__ __launch_bounds__(256) void fused_gemm(const float* __restrict__ h,
                                                  float* __restrict__ out, int M) {
    __shared__ float As[BK][BM];   // transposed: As[k][m]
    __shared__ float Bs[BK][BN];

    int tid = threadIdx.x;
    int tx = tid & 15;     // N direction (16)
    int ty = tid >> 4;     // M direction (16)
    int row0 = blockIdx.x * BM;

    unsigned long long acc[TM][TN / 2];
    #pragma unroll
    for (int m = 0; m < TM; m++)
        #pragma unroll
        for (int j = 0; j < TN / 2; j++) acc[m][j] = 0ULL;   // packed (0.f, 0.f)

    for (int k0 = 0; k0 < 256; k0 += BK) {
        const float* Abase = (k0 < 128) ? (h + k0) : (g_msg + (k0 - 128));
        // A tile: 128 rows x 16 k = 512 float4, 2 per thread
        #pragma unroll
        for (int l = 0; l < 2; l++) {
            int idx = tid + l * 256;
            int r = idx >> 2;             // tile row
            int c = (idx & 3) * 4;        // k offset within tile
            float4 v = make_float4(0.f, 0.f, 0.f, 0.f);
            int gr = row0 + r;
            if (gr < M)
                v = *reinterpret_cast<const float4*>(Abase + (size_t)gr * DIM + c);
            As[c + 0][r] = v.x; As[c + 1][r] = v.y;
            As[c + 2][r] = v.z; As[c + 3][r] = v.w;
        }
        // B tile: 16 k x 128 cols = 512 float4, 2 per thread
        #pragma unroll
        for (int l = 0; l < 2; l++) {
            int idx = tid + l * 256;
            int r = idx >> 5;             // k row (32 float4 per row)
            int c = (idx & 31) * 4;
            *reinterpret_cast<float4*>(&Bs[r][c]) =
                *reinterpret_cast<const float4*>(g_W + (size_t)(k0 + r) * 128 + c);
        }
        __syncthreads();

        #pragma unroll
        for (int kk = 0; kk < BK; kk++) {
            float a[TM];
            #pragma unroll
            for (int m = 0; m < TM; m += 4) {
                float4 t = *reinterpret_cast<const float4*>(&As[kk][ty * TM + m]);
                a[m] = t.x; a[m + 1] = t.y; a[m + 2] = t.z; a[m + 3] = t.w;
            }
            unsigned long long b2v[4];
            const unsigned long long* bp =
                reinterpret_cast<const unsigned long long*>(&Bs[kk][tx * TN]);
            b2v[0] = bp[0]; b2v[1] = bp[1]; b2v[2] = bp[2]; b2v[3] = bp[3];
            #pragma unroll
            for (int m = 0; m < TM; m++) {
                unsigned long long aa;
                asm("mov.b64 %0, {%1, %1};" : "=l"(aa) : "f"(a[m]));
                #pragma unroll
                for (int j = 0; j < 4; j++)
                    asm("fma.rn.f32x2 %0, %1, %2, %0;"
                        : "+l"(acc[m][j]) : "l"(aa), "l"(b2v[j]));
            }
        }
        __syncthreads();
    }

    // epilogue: + bias, relu, store
    float bias[TN];
    #pragma unroll
    for (int j = 0; j < TN; j++) bias[j] = g_b[tx * TN + j];

    #pragma unroll
    for (int m = 0; m < TM; m++) {
        int gr = row0 + ty * TM + m;
        if (gr >= M) continue;
        float res[TN];
        #pragma unroll
        for (int j = 0; j < 4; j++) {
            float lo, hi;
            asm("mov.b64 {%0, %1}, %2;" : "=f"(lo), "=f"(hi) : "l"(acc[m][j]));
            res[2 * j] = lo; res[2 * j + 1] = hi;
        }
        float4 o0, o1;
        o0.x = fmaxf(res[0] + bias[0], 0.f);
        o0.y = fmaxf(res[1] + bias[1], 0.f);
        o0.z = fmaxf(res[2] + bias[2], 0.f);
        o0.w = fmaxf(res[3] + bias[3], 0.f);
        o1.x = fmaxf(res[4] + bias[4], 0.f);
        o1.y = fmaxf(res[5] + bias[5], 0.f);
        o1.z = fmaxf(res[6] + bias[6], 0.f);
        o1.w = fmaxf(res[7] + bias[7], 0.f);
        float* op = out + (size_t)gr * DIM + tx * TN;
        *reinterpret_cast<float4*>(op) = o0;
        *reinterpret_cast<float4*>(op + 4) = o1;
    }
}

// ---------------------------------------------------------------------------
extern "C" void kernel_launch(void* const* d_in, const int* in_sizes, int n_in,
                              void* d_out, int out_size) {
    const float* h  = (const float*)d_in[0];
    const int* src  = (const int*)d_in[1];
    const int* dst  = (const int*)d_in[2];
    const float* W1 = (const float*)d_in[3];
    const float* b1 = (const float*)d_in[4];
    const float* W2 = (const float*)d_in[5];
    const float* b2 = (const float*)d_in[6];
    float* out = (float*)d_out;

    int N = in_sizes[0] / DIM;
    int E = in_sizes[1];

    fuse_weights<<<257, 128>>>(W1, b1, W2, b2);

    int total4 = N * (DIM / 4);
    zero_buffers<<<(total4 + 255) / 256, 256>>>(N);

    // one warp per edge
    long long threads = (long long)E * 32;
    scatter_edges<<<(int)((threads + 255) / 256), 256>>>(h, src, dst, E);

    scale_msg<<<(total4 + 255) / 256, 256>>>(N);

    fused_gemm<<<(N + BM - 1) / BM, 256>>>(h, out, N);
}